// round 1
// baseline (speedup 1.0000x reference)
#include <cuda_runtime.h>

#define NN   50000
#define EE   800000
#define HH   64
#define EAD  16
#define LLAY 5
#define GG   512
#define IN2  80
#define FD   320   // L*H

// ---------------- device scratch (no allocations allowed) ----------------
__device__ int   g_flag64;
__device__ int   g_cnt[NN];
__device__ int   g_off[NN + 1];
__device__ int   g_cur[NN];
__device__ int   g_srcS[EE];
__device__ __align__(16) float g_eaS[(size_t)EE * EAD];   // edge_attr, sorted by dst
__device__ __align__(16) float g_t1[(size_t)NN * HH];     // also reused as u
__device__ __align__(16) float g_agg[(size_t)NN * HH];    // also reused as h
__device__ __align__(16) float g_xA[(size_t)NN * HH];
__device__ __align__(16) float g_xB[(size_t)NN * HH];
__device__ float g_pool[(size_t)GG * FD];

// ---------------- helpers ----------------
__device__ __forceinline__ int loadIdx(const void* p, long long i, int is64) {
    if (is64) return (int)((const long long*)p)[i];
    return ((const int*)p)[i];
}

// ---------------- setup kernels ----------------
__global__ void kDetect(const void* ei) {
    const int* p = (const int*)ei;
    // int64 data => high words (odd int32 positions) are 0 for values < 2^31
    g_flag64 = (p[1] == 0 && p[3] == 0 && p[5] == 0 && p[7] == 0) ? 1 : 0;
}

__global__ void kZero() {
    int i = blockIdx.x * blockDim.x + threadIdx.x;
    if (i < NN) g_cnt[i] = 0;
    if (i < GG * FD) g_pool[i] = 0.f;
}

__global__ void kCount(const void* __restrict__ ei) {
    int e = blockIdx.x * blockDim.x + threadIdx.x;
    if (e >= EE) return;
    int f = g_flag64;
    int s = loadIdx(ei, e, f);
    int d = loadIdx(ei, (long long)EE + e, f);
    if (s != d) atomicAdd(&g_cnt[d], 1);
}

__global__ void kScan() {   // 1 block, 1024 threads: exclusive scan of g_cnt -> g_off,g_cur
    __shared__ int wsum[32];
    __shared__ int carry;
    int tid = threadIdx.x;
    if (tid == 0) carry = 0;
    __syncthreads();
    for (int base = 0; base < NN; base += 1024) {
        int i = base + tid;
        int v = (i < NN) ? g_cnt[i] : 0;
        int x = v;
#pragma unroll
        for (int o = 1; o < 32; o <<= 1) {
            int t = __shfl_up_sync(0xffffffffu, x, o);
            if ((tid & 31) >= o) x += t;
        }
        if ((tid & 31) == 31) wsum[tid >> 5] = x;
        __syncthreads();
        if (tid < 32) {
            int y = wsum[tid];
#pragma unroll
            for (int o = 1; o < 32; o <<= 1) {
                int t = __shfl_up_sync(0xffffffffu, y, o);
                if (tid >= o) y += t;
            }
            wsum[tid] = y;
        }
        __syncthreads();
        int add = (tid >= 32) ? wsum[(tid >> 5) - 1] : 0;
        int incl = x + add;
        int c0 = carry;
        if (i < NN) { int ex = c0 + incl - v; g_off[i] = ex; g_cur[i] = ex; }
        __syncthreads();
        if (tid == 1023) carry = c0 + incl;
        __syncthreads();
    }
    if (tid == 0) g_off[NN] = carry;
}

__global__ void kScatter(const void* __restrict__ ei, const float* __restrict__ ea) {
    int e = blockIdx.x * blockDim.x + threadIdx.x;
    if (e >= EE) return;
    int f = g_flag64;
    int s = loadIdx(ei, e, f);
    int d = loadIdx(ei, (long long)EE + e, f);
    if (s == d) return;
    int pos = atomicAdd(&g_cur[d], 1);
    g_srcS[pos] = s;
    const float4* s4 = (const float4*)(ea + (size_t)e * EAD);
    float4* d4 = (float4*)(g_eaS + (size_t)pos * EAD);
    d4[0] = s4[0]; d4[1] = s4[1]; d4[2] = s4[2]; d4[3] = s4[3];
}

// ---------------- per-layer: edge aggregation ----------------
// agg[n][c] = sum over incoming non-self edges of relu(t1[src][c] + (ea@W1b)[c] + b1[c])
__global__ __launch_bounds__(256) void kAgg(const float* __restrict__ w1full,
                                            const float* __restrict__ b1) {
    int lane = threadIdx.x & 31;
    int warp = threadIdx.x >> 5;
    const float* w1b = w1full + 64 * HH;   // rows 64..79 of the 80x64 matrix
    float wA[16], wB[16];
#pragma unroll
    for (int k = 0; k < 16; k++) {
        wA[k] = w1b[k * HH + lane];
        wB[k] = w1b[k * HH + lane + 32];
    }
    float b1A = b1[lane], b1B = b1[lane + 32];
    int stride = gridDim.x * 8;
    for (int n = blockIdx.x * 8 + warp; n < NN; n += stride) {
        int beg = g_off[n], end = g_off[n + 1];
        float accA = 0.f, accB = 0.f;
#pragma unroll 2
        for (int j = beg; j < end; j++) {
            int s = g_srcS[j];
            const float4* e4 = (const float4*)(g_eaS + (size_t)j * EAD);
            float ev[16];
            ((float4*)ev)[0] = e4[0];
            ((float4*)ev)[1] = e4[1];
            ((float4*)ev)[2] = e4[2];
            ((float4*)ev)[3] = e4[3];
            float tA = b1A, tB = b1B;
#pragma unroll
            for (int k = 0; k < 16; k++) {
                tA = fmaf(ev[k], wA[k], tA);
                tB = fmaf(ev[k], wB[k], tB);
            }
            float gA = g_t1[(size_t)s * HH + lane];
            float gB = g_t1[(size_t)s * HH + lane + 32];
            accA += fmaxf(tA + gA, 0.f);
            accB += fmaxf(tB + gB, 0.f);
        }
        g_agg[(size_t)n * HH + lane] = accA;
        g_agg[(size_t)n * HH + lane + 32] = accB;
    }
}

// ---------------- generic N x 64 x 64 GEMM with fused epilogues ----------------
#define M_PLAIN 0   // out = A@W                      (t1 = x @ W1a)
#define M_U     1   // out = A@W + (1+eps)*X2 + cnt*b2
#define M_RELU  2   // out = relu(A@W + bias)
#define M_OUT   3   // out = A@W + bias; pool[batch[r]] += out

// buffer selectors (avoid host-side symbol addresses entirely)
__device__ __forceinline__ const float* pickIn(int sel, const float* xin) {
    switch (sel) {
        case 0: return g_t1;
        case 1: return g_agg;
        case 2: return g_xA;
        case 3: return g_xB;
        default: return xin;
    }
}
__device__ __forceinline__ float* pickOut(int sel) {
    switch (sel) {
        case 0: return g_t1;
        case 1: return g_agg;
        case 2: return g_xA;
        default: return g_xB;
    }
}

__global__ __launch_bounds__(256) void kGemm(int selA, const float* __restrict__ xin,
                                             const float* __restrict__ W, int selOut,
                                             int mode, const float* __restrict__ bias,
                                             int selX2, const float* __restrict__ xin2,
                                             const float* __restrict__ epsPtr,
                                             const void* __restrict__ batch, int layer) {
    __shared__ __align__(16) float xsh[4][HH];
    const float* A = pickIn(selA, xin);
    const float* X2 = (mode == M_U) ? pickIn(selX2, xin2) : nullptr;
    float* Out = pickOut(selOut);
    int c = threadIdx.x & 63;
    int rs = threadIdx.x >> 6;
    float wreg[64];
#pragma unroll
    for (int k = 0; k < 64; k++) wreg[k] = W[k * HH + c];
    float bv = bias ? bias[c] : 0.f;
    float ope = (mode == M_U) ? 1.f + epsPtr[0] : 0.f;
    int f64 = g_flag64;
    const int RB = NN / 4;   // 12500, exact
    for (int rb = blockIdx.x; rb < RB; rb += gridDim.x) {
        int r = rb * 4 + rs;
        __syncthreads();
        xsh[rs][c] = A[(size_t)r * HH + c];
        __syncthreads();
        float acc = 0.f;
        const float4* xv4 = (const float4*)xsh[rs];
#pragma unroll
        for (int k4 = 0; k4 < 16; k4++) {
            float4 xv = xv4[k4];
            acc = fmaf(xv.x, wreg[4 * k4 + 0], acc);
            acc = fmaf(xv.y, wreg[4 * k4 + 1], acc);
            acc = fmaf(xv.z, wreg[4 * k4 + 2], acc);
            acc = fmaf(xv.w, wreg[4 * k4 + 3], acc);
        }
        size_t oi = (size_t)r * HH + c;
        if (mode == M_PLAIN) {
            Out[oi] = acc;
        } else if (mode == M_U) {
            int cnt = g_off[r + 1] - g_off[r];
            Out[oi] = acc + ope * X2[oi] + (float)cnt * bv;
        } else if (mode == M_RELU) {
            Out[oi] = fmaxf(acc + bv, 0.f);
        } else {
            acc += bv;
            Out[oi] = acc;
            int g = f64 ? (int)((const long long*)batch)[r] : ((const int*)batch)[r];
            atomicAdd(&g_pool[(size_t)g * FD + layer * HH + c], acc);
        }
    }
}

// ---------------- final MLP: [512,320] @ [320,320] -> relu -> @ [320,1] ----------------
__global__ __launch_bounds__(320) void kFinal(const float* __restrict__ fw1,
                                              const float* __restrict__ fb1,
                                              const float* __restrict__ fw2,
                                              const float* __restrict__ fb2,
                                              float* __restrict__ out) {
    __shared__ float fsh[8][FD];
    __shared__ float hsh[8][FD];
    int tid = threadIdx.x;
    int gbase = blockIdx.x * 8;
    for (int i = tid; i < 8 * FD; i += 320) {
        int gg = i / FD, k = i % FD;
        fsh[gg][k] = g_pool[(size_t)(gbase + gg) * FD + k];
    }
    __syncthreads();
    float acc[8] = {0, 0, 0, 0, 0, 0, 0, 0};
    for (int k = 0; k < FD; k++) {
        float w = fw1[(size_t)k * FD + tid];
#pragma unroll
        for (int gg = 0; gg < 8; gg++) acc[gg] = fmaf(fsh[gg][k], w, acc[gg]);
    }
    float b = fb1[tid];
#pragma unroll
    for (int gg = 0; gg < 8; gg++) hsh[gg][tid] = fmaxf(acc[gg] + b, 0.f);
    __syncthreads();
    int warp = tid >> 5, lane = tid & 31;
    if (warp < 8) {
        float s = 0.f;
        for (int k = lane; k < FD; k += 32) s += hsh[warp][k] * fw2[k];
#pragma unroll
        for (int o = 16; o; o >>= 1) s += __shfl_down_sync(0xffffffffu, s, o);
        if (lane == 0) out[gbase + warp] = s + fb2[0];
    }
}

// ---------------- launch ----------------
extern "C" void kernel_launch(void* const* d_in, const int* in_sizes, int n_in,
                              void* d_out, int out_size) {
    const float* x    = (const float*)d_in[0];
    const void*  ei   = d_in[1];
    const float* ea   = (const float*)d_in[2];
    const void*  bat  = d_in[3];
    const float* n2w1 = (const float*)d_in[4];
    const float* n2b1 = (const float*)d_in[5];
    const float* n2w2 = (const float*)d_in[6];
    const float* n2b2 = (const float*)d_in[7];
    const float* n1w1 = (const float*)d_in[8];
    const float* n1b1 = (const float*)d_in[9];
    const float* n1w2 = (const float*)d_in[10];
    const float* n1b2 = (const float*)d_in[11];
    const float* fw1  = (const float*)d_in[12];
    const float* fb1  = (const float*)d_in[13];
    const float* fw2  = (const float*)d_in[14];
    const float* fb2  = (const float*)d_in[15];
    const float* eps  = (const float*)d_in[16];

    kDetect<<<1, 1>>>(ei);
    kZero<<<(GG * FD + 255) / 256, 256>>>();
    kCount<<<EE / 256, 256>>>(ei);
    kScan<<<1, 1024>>>();
    kScatter<<<EE / 256, 256>>>(ei, ea);

    // buffer selectors: 0=t1(/u), 1=agg(/h), 2=xA, 3=xB, 4=external
    int xSel = 4;                 // layer-0 input is d_in[0]
    const float* xPtr = x;
    for (int l = 0; l < LLAY; l++) {
        const float* W1 = n2w1 + (size_t)l * IN2 * HH;   // W1a = rows 0..63, W1b = rows 64..79
        const float* b1 = n2b1 + (size_t)l * HH;
        const float* W2 = n2w2 + (size_t)l * HH * HH;
        const float* b2 = n2b2 + (size_t)l * HH;
        const float* V1 = n1w1 + (size_t)l * HH * HH;
        const float* c1 = n1b1 + (size_t)l * HH;
        const float* V2 = n1w2 + (size_t)l * HH * HH;
        const float* c2 = n1b2 + (size_t)l * HH;
        int xNextSel = (l & 1) ? 3 : 2;   // alternate xA/xB

        // t1 = x @ W1a
        kGemm<<<1184, 256>>>(xSel, xPtr, W1, 0, M_PLAIN, nullptr, 0, nullptr, nullptr, nullptr, l);
        // agg = sum relu(t1[src] + ea@W1b + b1)
        kAgg<<<888, 256>>>(W1, b1);
        // u = agg@W2 + (1+eps)*x + cnt*b2   (u overwrites t1)
        kGemm<<<1184, 256>>>(1, nullptr, W2, 0, M_U, b2, xSel, xPtr, eps, nullptr, l);
        // h = relu(u@V1 + c1)               (h overwrites agg)
        kGemm<<<1184, 256>>>(0, nullptr, V1, 1, M_RELU, c1, 0, nullptr, nullptr, nullptr, l);
        // x_next = h@V2 + c2 ; pool[batch]+=x_next
        kGemm<<<1184, 256>>>(1, nullptr, V2, xNextSel, M_OUT, c2, 0, nullptr, nullptr, bat, l);

        xSel = xNextSel;
        xPtr = nullptr;
    }

    kFinal<<<GG / 8, 320>>>(fw1, fb1, fw2, fb2, (float*)d_out);
}

// round 2
// speedup vs baseline: 1.0891x; 1.0891x over previous
#include <cuda_runtime.h>

#define NN   50000
#define EE   800000
#define HH   64
#define EAD  16
#define LLAY 5
#define GG   512
#define IN2  80
#define FD   320   // L*H
#define NBLK 49    // ceil(NN/1024)

// ---------------- device scratch (no allocations allowed) ----------------
__device__ int   g_flag64;
__device__ int   g_cnt[NN];        // per-node non-self in-degree (kept after scan)
__device__ int   g_off[NN + 1];
__device__ int   g_cur[NN];
__device__ int   g_bsum[NBLK];
__device__ int   g_srcS[EE];
__device__ __align__(16) float g_eaS[(size_t)EE * EAD];   // edge_attr, sorted by dst
__device__ __align__(16) float g_t1[(size_t)NN * HH];     // x@W1a + b1 (per current layer)
__device__ __align__(16) float g_agg[(size_t)NN * HH];
__device__ __align__(16) float g_xA[(size_t)NN * HH];
__device__ __align__(16) float g_xB[(size_t)NN * HH];
__device__ float g_pool[(size_t)GG * FD];

// ---------------- helpers ----------------
__device__ __forceinline__ int loadIdx(const void* p, long long i, int is64) {
    if (is64) return (int)((const long long*)p)[i];
    return ((const int*)p)[i];
}

__device__ __forceinline__ const float* pickIn(int sel, const float* xin) {
    switch (sel) {
        case 2: return g_xA;
        case 3: return g_xB;
        default: return xin;
    }
}
__device__ __forceinline__ float* pickOut(int sel) {
    return (sel == 2) ? g_xA : g_xB;
}

// ---------------- setup kernels ----------------
__global__ void kDetect(const void* ei) {
    const int* p = (const int*)ei;
    g_flag64 = (p[1] == 0 && p[3] == 0 && p[5] == 0 && p[7] == 0) ? 1 : 0;
}

__global__ void kZero() {
    int i = blockIdx.x * blockDim.x + threadIdx.x;
    if (i < NN) g_cnt[i] = 0;
    if (i < GG * FD) g_pool[i] = 0.f;
}

__global__ void kCount(const void* __restrict__ ei) {
    int e = blockIdx.x * blockDim.x + threadIdx.x;
    if (e >= EE) return;
    int f = g_flag64;
    int s = loadIdx(ei, e, f);
    int d = loadIdx(ei, (long long)EE + e, f);
    if (s != d) atomicAdd(&g_cnt[d], 1);
}

// ---- 3-phase parallel exclusive scan of g_cnt -> g_off / g_cur ----
__global__ void kScanA() {
    __shared__ int wsum[32];
    int tid = threadIdx.x, lane = tid & 31, wid = tid >> 5;
    int i = blockIdx.x * 1024 + tid;
    int v = (i < NN) ? g_cnt[i] : 0;
    int x = v;
#pragma unroll
    for (int o = 1; o < 32; o <<= 1) {
        int t = __shfl_up_sync(0xffffffffu, x, o);
        if (lane >= o) x += t;
    }
    if (lane == 31) wsum[wid] = x;
    __syncthreads();
    if (tid < 32) {
        int y = wsum[tid];
#pragma unroll
        for (int o = 1; o < 32; o <<= 1) {
            int t = __shfl_up_sync(0xffffffffu, y, o);
            if (tid >= o) y += t;
        }
        wsum[tid] = y;
    }
    __syncthreads();
    int incl = x + (wid ? wsum[wid - 1] : 0);
    if (i < NN) g_off[i] = incl - v;           // block-local exclusive
    if (tid == 1023) g_bsum[blockIdx.x] = incl;
}
__global__ void kScanB() {
    if (threadIdx.x == 0) {
        int s = 0;
        for (int b = 0; b < NBLK; b++) { int t = g_bsum[b]; g_bsum[b] = s; s += t; }
        g_off[NN] = s;
    }
}
__global__ void kScanC() {
    int i = blockIdx.x * 1024 + threadIdx.x;
    if (i < NN) {
        int v = g_off[i] + g_bsum[blockIdx.x];
        g_off[i] = v;
        g_cur[i] = v;
    }
}

__global__ void kScatter(const void* __restrict__ ei, const float* __restrict__ ea) {
    int e = blockIdx.x * blockDim.x + threadIdx.x;
    if (e >= EE) return;
    int f = g_flag64;
    int s = loadIdx(ei, e, f);
    int d = loadIdx(ei, (long long)EE + e, f);
    if (s == d) return;
    int pos = atomicAdd(&g_cur[d], 1);
    g_srcS[pos] = s;
    const float4* s4 = (const float4*)(ea + (size_t)e * EAD);
    float4* d4 = (float4*)(g_eaS + (size_t)pos * EAD);
    d4[0] = s4[0]; d4[1] = s4[1]; d4[2] = s4[2]; d4[3] = s4[3];
}

// ---------------- 32-row x 64 x 64 register-tiled GEMM core ----------------
// thread (c = tid&63, rs = tid>>6) computes rows {i*4+rs} x column c; 8 independent chains
__device__ __forceinline__ void gemmTile(const float (*sIn)[64], const float* w, int rs,
                                         float* acc) {
#pragma unroll
    for (int i = 0; i < 8; i++) acc[i] = 0.f;
#pragma unroll
    for (int k4 = 0; k4 < 16; k4++) {
#pragma unroll
        for (int i = 0; i < 8; i++) {
            float4 v = *(const float4*)&sIn[i * 4 + rs][k4 * 4];
            acc[i] = fmaf(v.x, w[4 * k4 + 0], acc[i]);
            acc[i] = fmaf(v.y, w[4 * k4 + 1], acc[i]);
            acc[i] = fmaf(v.z, w[4 * k4 + 2], acc[i]);
            acc[i] = fmaf(v.w, w[4 * k4 + 3], acc[i]);
        }
    }
}

// ---------------- initial t1 = x @ W1a + b1 ----------------
__global__ __launch_bounds__(256) void kT1(const float* __restrict__ X,
                                           const float* __restrict__ W,
                                           const float* __restrict__ B) {
    __shared__ __align__(16) float sIn[32][64];
    int c = threadIdx.x & 63, rs = threadIdx.x >> 6;
    int base = blockIdx.x * 32;
    for (int i = rs; i < 32; i += 4) {
        int r = base + i;
        sIn[i][c] = (r < NN) ? X[(size_t)r * HH + c] : 0.f;
    }
    __syncthreads();
    float w[64];
#pragma unroll
    for (int k = 0; k < 64; k++) w[k] = W[k * HH + c];
    float b = B[c];
    float acc[8];
    gemmTile(sIn, w, rs, acc);
#pragma unroll
    for (int i = 0; i < 8; i++) {
        int r = base + i * 4 + rs;
        if (r < NN) g_t1[(size_t)r * HH + c] = acc[i] + b;
    }
}

// ---------------- per-layer edge aggregation (pipelined) ----------------
// agg[n][c] = sum over incoming non-self edges of relu(t1[src][c] + (ea@W1b)[c])
__global__ __launch_bounds__(256) void kAgg(const float* __restrict__ w1full) {
    int lane = threadIdx.x & 31;
    int warp = threadIdx.x >> 5;
    const float* w1b = w1full + 64 * HH;   // rows 64..79 of the 80x64 matrix
    float wA[16], wB[16];
#pragma unroll
    for (int k = 0; k < 16; k++) {
        wA[k] = w1b[k * HH + lane];
        wB[k] = w1b[k * HH + lane + 32];
    }
    int n = blockIdx.x * 8 + warp;
    if (n >= NN) return;
    int beg = g_off[n], end = g_off[n + 1];
    float accA = 0.f, accB = 0.f;

    int j = beg;
    float4 e0, e1, e2, e3;
    float gA = 0.f, gB = 0.f;
    if (j < end) {
        int s = g_srcS[j];
        const float4* p = (const float4*)(g_eaS + (size_t)j * EAD);
        e0 = p[0]; e1 = p[1]; e2 = p[2]; e3 = p[3];
        gA = g_t1[(size_t)s * HH + lane];
        gB = g_t1[(size_t)s * HH + lane + 32];
    }
    while (j < end) {
        int jn = j + 1;
        float4 f0, f1, f2, f3;
        float hA = 0.f, hB = 0.f;
        if (jn < end) {                      // prefetch next edge
            int s = g_srcS[jn];
            const float4* p = (const float4*)(g_eaS + (size_t)jn * EAD);
            f0 = p[0]; f1 = p[1]; f2 = p[2]; f3 = p[3];
            hA = g_t1[(size_t)s * HH + lane];
            hB = g_t1[(size_t)s * HH + lane + 32];
        }
        float tA = gA, tB = gB;
        tA = fmaf(e0.x, wA[0], tA);  tB = fmaf(e0.x, wB[0], tB);
        tA = fmaf(e0.y, wA[1], tA);  tB = fmaf(e0.y, wB[1], tB);
        tA = fmaf(e0.z, wA[2], tA);  tB = fmaf(e0.z, wB[2], tB);
        tA = fmaf(e0.w, wA[3], tA);  tB = fmaf(e0.w, wB[3], tB);
        tA = fmaf(e1.x, wA[4], tA);  tB = fmaf(e1.x, wB[4], tB);
        tA = fmaf(e1.y, wA[5], tA);  tB = fmaf(e1.y, wB[5], tB);
        tA = fmaf(e1.z, wA[6], tA);  tB = fmaf(e1.z, wB[6], tB);
        tA = fmaf(e1.w, wA[7], tA);  tB = fmaf(e1.w, wB[7], tB);
        tA = fmaf(e2.x, wA[8], tA);  tB = fmaf(e2.x, wB[8], tB);
        tA = fmaf(e2.y, wA[9], tA);  tB = fmaf(e2.y, wB[9], tB);
        tA = fmaf(e2.z, wA[10], tA); tB = fmaf(e2.z, wB[10], tB);
        tA = fmaf(e2.w, wA[11], tA); tB = fmaf(e2.w, wB[11], tB);
        tA = fmaf(e3.x, wA[12], tA); tB = fmaf(e3.x, wB[12], tB);
        tA = fmaf(e3.y, wA[13], tA); tB = fmaf(e3.y, wB[13], tB);
        tA = fmaf(e3.z, wA[14], tA); tB = fmaf(e3.z, wB[14], tB);
        tA = fmaf(e3.w, wA[15], tA); tB = fmaf(e3.w, wB[15], tB);
        accA += fmaxf(tA, 0.f);
        accB += fmaxf(tB, 0.f);
        e0 = f0; e1 = f1; e2 = f2; e3 = f3;
        gA = hA; gB = hB;
        j = jn;
    }
    g_agg[(size_t)n * HH + lane] = accA;
    g_agg[(size_t)n * HH + lane + 32] = accB;
}

// ---------------- fused node update ----------------
// u = agg@W2 + (1+eps)*x + cnt*b2      (smem)
// h = relu(u@V1 + c1)                  (smem)
// xn = h@V2 + c2 -> global xOut, pool atomic
// t1' = xn@W1a_next + b1_next -> g_t1  (if W1n != null)
__global__ __launch_bounds__(256) void kNode(int xSel, const float* __restrict__ xExt,
                                             int xOutSel,
                                             const float* __restrict__ W2,
                                             const float* __restrict__ b2,
                                             const float* __restrict__ V1,
                                             const float* __restrict__ c1,
                                             const float* __restrict__ V2,
                                             const float* __restrict__ c2,
                                             const float* __restrict__ W1n,
                                             const float* __restrict__ b1n,
                                             const float* __restrict__ epsPtr,
                                             const void* __restrict__ batch, int layer) {
    __shared__ __align__(16) float sA[32][64];
    __shared__ __align__(16) float sB[32][64];
    int c = threadIdx.x & 63, rs = threadIdx.x >> 6;
    int base = blockIdx.x * 32;
    const float* X = pickIn(xSel, xExt);
    float* Xo = pickOut(xOutSel);

    for (int i = rs; i < 32; i += 4) {
        int r = base + i;
        sA[i][c] = (r < NN) ? g_agg[(size_t)r * HH + c] : 0.f;
    }
    __syncthreads();

    float w[64], acc[8];

    // ---- stage 1: u ----
#pragma unroll
    for (int k = 0; k < 64; k++) w[k] = W2[k * HH + c];
    gemmTile(sA, w, rs, acc);
    {
        float bv = b2[c];
        float ope = 1.f + epsPtr[0];
#pragma unroll
        for (int i = 0; i < 8; i++) {
            int rr = i * 4 + rs, r = base + rr;
            float xv = (r < NN) ? X[(size_t)r * HH + c] : 0.f;
            float cnt = (r < NN) ? (float)g_cnt[r] : 0.f;
            sB[rr][c] = acc[i] + ope * xv + cnt * bv;
        }
    }
    __syncthreads();

    // ---- stage 2: h = relu(u@V1 + c1) ----
#pragma unroll
    for (int k = 0; k < 64; k++) w[k] = V1[k * HH + c];
    gemmTile(sB, w, rs, acc);
    {
        float bv = c1[c];
#pragma unroll
        for (int i = 0; i < 8; i++) sA[i * 4 + rs][c] = fmaxf(acc[i] + bv, 0.f);
    }
    __syncthreads();

    // ---- stage 3: xn = h@V2 + c2 ----
#pragma unroll
    for (int k = 0; k < 64; k++) w[k] = V2[k * HH + c];
    gemmTile(sA, w, rs, acc);
    {
        float bv = c2[c];
        int f64 = g_flag64;
#pragma unroll
        for (int i = 0; i < 8; i++) {
            int rr = i * 4 + rs, r = base + rr;
            float v = acc[i] + bv;
            sB[rr][c] = v;
            if (r < NN) {
                Xo[(size_t)r * HH + c] = v;
                int g = f64 ? (int)((const long long*)batch)[r] : ((const int*)batch)[r];
                atomicAdd(&g_pool[(size_t)g * FD + layer * HH + c], v);
            }
        }
    }

    // ---- stage 4: t1_next = xn@W1a_next + b1_next ----
    if (W1n) {
        __syncthreads();
#pragma unroll
        for (int k = 0; k < 64; k++) w[k] = W1n[k * HH + c];
        gemmTile(sB, w, rs, acc);
        float bv = b1n[c];
#pragma unroll
        for (int i = 0; i < 8; i++) {
            int r = base + i * 4 + rs;
            if (r < NN) g_t1[(size_t)r * HH + c] = acc[i] + bv;
        }
    }
}

// ---------------- final MLP ----------------
__global__ __launch_bounds__(320) void kFinal(const float* __restrict__ fw1,
                                              const float* __restrict__ fb1,
                                              const float* __restrict__ fw2,
                                              const float* __restrict__ fb2,
                                              float* __restrict__ out) {
    __shared__ float fsh[8][FD];
    __shared__ float hsh[8][FD];
    int tid = threadIdx.x;
    int gbase = blockIdx.x * 8;
    for (int i = tid; i < 8 * FD; i += 320) {
        int gg = i / FD, k = i % FD;
        fsh[gg][k] = g_pool[(size_t)(gbase + gg) * FD + k];
    }
    __syncthreads();
    float acc[8] = {0, 0, 0, 0, 0, 0, 0, 0};
    for (int k = 0; k < FD; k++) {
        float w = fw1[(size_t)k * FD + tid];
#pragma unroll
        for (int gg = 0; gg < 8; gg++) acc[gg] = fmaf(fsh[gg][k], w, acc[gg]);
    }
    float b = fb1[tid];
#pragma unroll
    for (int gg = 0; gg < 8; gg++) hsh[gg][tid] = fmaxf(acc[gg] + b, 0.f);
    __syncthreads();
    int warp = tid >> 5, lane = tid & 31;
    if (warp < 8) {
        float s = 0.f;
        for (int k = lane; k < FD; k += 32) s += hsh[warp][k] * fw2[k];
#pragma unroll
        for (int o = 16; o; o >>= 1) s += __shfl_down_sync(0xffffffffu, s, o);
        if (lane == 0) out[gbase + warp] = s + fb2[0];
    }
}

// ---------------- launch ----------------
extern "C" void kernel_launch(void* const* d_in, const int* in_sizes, int n_in,
                              void* d_out, int out_size) {
    const float* x    = (const float*)d_in[0];
    const void*  ei   = d_in[1];
    const float* ea   = (const float*)d_in[2];
    const void*  bat  = d_in[3];
    const float* n2w1 = (const float*)d_in[4];
    const float* n2b1 = (const float*)d_in[5];
    const float* n2w2 = (const float*)d_in[6];
    const float* n2b2 = (const float*)d_in[7];
    const float* n1w1 = (const float*)d_in[8];
    const float* n1b1 = (const float*)d_in[9];
    const float* n1w2 = (const float*)d_in[10];
    const float* n1b2 = (const float*)d_in[11];
    const float* fw1  = (const float*)d_in[12];
    const float* fb1  = (const float*)d_in[13];
    const float* fw2  = (const float*)d_in[14];
    const float* fb2  = (const float*)d_in[15];
    const float* eps  = (const float*)d_in[16];

    kDetect<<<1, 1>>>(ei);
    kZero<<<(GG * FD + 255) / 256, 256>>>();
    kCount<<<EE / 256, 256>>>(ei);
    kScanA<<<NBLK, 1024>>>();
    kScanB<<<1, 32>>>();
    kScanC<<<NBLK, 1024>>>();
    kScatter<<<EE / 256, 256>>>(ei, ea);

    // initial t1 = x @ W1a_0 + b1_0
    kT1<<<(NN + 31) / 32, 256>>>(x, n2w1, n2b1);

    int xSel = 4;                 // external
    const float* xPtr = x;
    for (int l = 0; l < LLAY; l++) {
        const float* W2 = n2w2 + (size_t)l * HH * HH;
        const float* b2 = n2b2 + (size_t)l * HH;
        const float* V1 = n1w1 + (size_t)l * HH * HH;
        const float* c1 = n1b1 + (size_t)l * HH;
        const float* V2 = n1w2 + (size_t)l * HH * HH;
        const float* c2 = n1b2 + (size_t)l * HH;
        const float* W1n = (l + 1 < LLAY) ? n2w1 + (size_t)(l + 1) * IN2 * HH : nullptr;
        const float* b1n = (l + 1 < LLAY) ? n2b1 + (size_t)(l + 1) * HH : nullptr;
        int xNextSel = (l & 1) ? 3 : 2;

        kAgg<<<(NN + 7) / 8, 256>>>(n2w1 + (size_t)l * IN2 * HH);
        kNode<<<(NN + 31) / 32, 256>>>(xSel, xPtr, xNextSel, W2, b2, V1, c1, V2, c2,
                                       W1n, b1n, eps, bat, l);

        xSel = xNextSel;
        xPtr = nullptr;
    }

    kFinal<<<GG / 8, 320>>>(fw1, fb1, fw2, fb2, (float*)d_out);
}

// round 3
// speedup vs baseline: 1.8168x; 1.6682x over previous
#include <cuda_runtime.h>

#define NN   50000
#define EE   800000
#define HH   64
#define EAD  16
#define LLAY 5
#define GG   512
#define IN2  80
#define FD   320   // L*H
#define NBLK 49    // ceil(NN/1024)
#define CHK  256   // edges staged per kAgg chunk

typedef unsigned long long ull;

// ---------------- device scratch ----------------
__device__ int   g_flag64;
__device__ int   g_cnt[NN];
__device__ int   g_off[NN + 1];
__device__ int   g_cur[NN];
__device__ int   g_bsum[NBLK];
__device__ int   g_srcS[EE];
__device__ __align__(16) float g_eaS[(size_t)EE * EAD];   // edge_attr sorted by dst
__device__ __align__(16) float g_t1[(size_t)NN * HH];     // x@W1a + b1
__device__ __align__(16) float g_agg[(size_t)NN * HH];
__device__ __align__(16) float g_xA[(size_t)NN * HH];
__device__ __align__(16) float g_xB[(size_t)NN * HH];
__device__ float g_pool[(size_t)GG * FD];

// ---------------- f32x2 packed helpers ----------------
__device__ __forceinline__ ull pk2(float a, float b) {
    ull r; asm("mov.b64 %0,{%1,%2};" : "=l"(r) : "f"(a), "f"(b)); return r;
}
__device__ __forceinline__ void upk2(ull v, float& a, float& b) {
    asm("mov.b64 {%0,%1},%2;" : "=f"(a), "=f"(b) : "l"(v));
}
__device__ __forceinline__ ull fma2(ull a, ull b, ull c) {
    ull d; asm("fma.rn.f32x2 %0,%1,%2,%3;" : "=l"(d) : "l"(a), "l"(b), "l"(c)); return d;
}

__device__ __forceinline__ int loadIdx(const void* p, long long i, int is64) {
    if (is64) return (int)((const long long*)p)[i];
    return ((const int*)p)[i];
}
__device__ __forceinline__ const float* pickIn(int sel, const float* xin) {
    switch (sel) { case 2: return g_xA; case 3: return g_xB; default: return xin; }
}
__device__ __forceinline__ float* pickOut(int sel) { return (sel == 2) ? g_xA : g_xB; }

// ---------------- setup ----------------
__global__ void kDetect(const void* ei) {
    const int* p = (const int*)ei;
    g_flag64 = (p[1] == 0 && p[3] == 0 && p[5] == 0 && p[7] == 0) ? 1 : 0;
}
__global__ void kZero() {
    int i = blockIdx.x * blockDim.x + threadIdx.x;
    if (i < NN) g_cnt[i] = 0;
    if (i < GG * FD) g_pool[i] = 0.f;
}
__global__ void kCount(const void* __restrict__ ei) {
    int e = blockIdx.x * blockDim.x + threadIdx.x;
    if (e >= EE) return;
    int f = g_flag64;
    int s = loadIdx(ei, e, f);
    int d = loadIdx(ei, (long long)EE + e, f);
    if (s != d) atomicAdd(&g_cnt[d], 1);
}
__global__ void kScanA() {
    __shared__ int wsum[32];
    int tid = threadIdx.x, lane = tid & 31, wid = tid >> 5;
    int i = blockIdx.x * 1024 + tid;
    int v = (i < NN) ? g_cnt[i] : 0;
    int x = v;
#pragma unroll
    for (int o = 1; o < 32; o <<= 1) {
        int t = __shfl_up_sync(0xffffffffu, x, o);
        if (lane >= o) x += t;
    }
    if (lane == 31) wsum[wid] = x;
    __syncthreads();
    if (tid < 32) {
        int y = wsum[tid];
#pragma unroll
        for (int o = 1; o < 32; o <<= 1) {
            int t = __shfl_up_sync(0xffffffffu, y, o);
            if (tid >= o) y += t;
        }
        wsum[tid] = y;
    }
    __syncthreads();
    int incl = x + (wid ? wsum[wid - 1] : 0);
    if (i < NN) g_off[i] = incl - v;
    if (tid == 1023) g_bsum[blockIdx.x] = incl;
}
__global__ void kScanB() {
    if (threadIdx.x == 0) {
        int s = 0;
        for (int b = 0; b < NBLK; b++) { int t = g_bsum[b]; g_bsum[b] = s; s += t; }
        g_off[NN] = s;
    }
}
__global__ void kScanC() {
    int i = blockIdx.x * 1024 + threadIdx.x;
    if (i < NN) {
        int v = g_off[i] + g_bsum[blockIdx.x];
        g_off[i] = v;
        g_cur[i] = v;
    }
}
__global__ void kScatter(const void* __restrict__ ei, const float* __restrict__ ea) {
    int e = blockIdx.x * blockDim.x + threadIdx.x;
    if (e >= EE) return;
    int f = g_flag64;
    int s = loadIdx(ei, e, f);
    int d = loadIdx(ei, (long long)EE + e, f);
    if (s == d) return;
    int pos = atomicAdd(&g_cur[d], 1);
    g_srcS[pos] = s;
    const float4* s4 = (const float4*)(ea + (size_t)e * EAD);
    float4* d4 = (float4*)(g_eaS + (size_t)pos * EAD);
    d4[0] = s4[0]; d4[1] = s4[1]; d4[2] = s4[2]; d4[3] = s4[3];
}

// ---------------- packed 32-row GEMM core ----------------
// sIn[rp][k] = f32x2(row 2rp [k], row 2rp+1 [k]).  thread (c=tid&63, rs=tid>>6)
// computes col c of rowpairs {rs, rs+4, rs+8, rs+12}.
__device__ __forceinline__ void gemmP(const ull (*sIn)[64], const float* w, int rs,
                                      ull* acc) {
#pragma unroll
    for (int i = 0; i < 4; i++) acc[i] = 0ull;
#pragma unroll
    for (int kp = 0; kp < 32; kp++) {
        ull wd0 = pk2(w[2 * kp], w[2 * kp]);
        ull wd1 = pk2(w[2 * kp + 1], w[2 * kp + 1]);
#pragma unroll
        for (int i = 0; i < 4; i++) {
            ulonglong2 v = *(const ulonglong2*)&sIn[rs + 4 * i][2 * kp];
            acc[i] = fma2(v.x, wd0, acc[i]);
            acc[i] = fma2(v.y, wd1, acc[i]);
        }
    }
}

// ---------------- t1 = x @ W1a + b1 (packed) ----------------
__global__ __launch_bounds__(256) void kT1(const float* __restrict__ X,
                                           const float* __restrict__ W,
                                           const float* __restrict__ B) {
    __shared__ __align__(16) ull sIn[16][64];
    int tid = threadIdx.x;
    int c = tid & 63, rs = tid >> 6;
    int base = blockIdx.x * 32;
    float* sf = (float*)sIn;
    for (int idx = tid; idx < 2048; idx += 256) {
        int r = idx >> 6, cc = idx & 63;
        int gr = base + r;
        sf[((r >> 1) * 64 + cc) * 2 + (r & 1)] = (gr < NN) ? X[(size_t)gr * HH + cc] : 0.f;
    }
    __syncthreads();
    float w[64];
#pragma unroll
    for (int k = 0; k < 64; k++) w[k] = W[k * HH + c];
    ull acc[4];
    gemmP(sIn, w, rs, acc);
    float b = B[c];
#pragma unroll
    for (int i = 0; i < 4; i++) {
        int r0 = base + 2 * (rs + 4 * i), r1 = r0 + 1;
        float a0, a1; upk2(acc[i], a0, a1);
        if (r0 < NN) g_t1[(size_t)r0 * HH + c] = a0 + b;
        if (r1 < NN) g_t1[(size_t)r1 * HH + c] = a1 + b;
    }
}

// ---------------- edge aggregation: smem-staged, 3-deep gather prefetch ----------------
// agg[n][c] = sum over incoming non-self edges of relu(t1[src][c] + (ea@W1b)[c])
__global__ __launch_bounds__(256) void kAgg(const float* __restrict__ w1full) {
    __shared__ __align__(16) float sea[CHK * EAD];   // 16 KB
    __shared__ int ssrc[CHK];
    int tid = threadIdx.x;
    int lane = tid & 31, warp = tid >> 5;
    const float* w1b = w1full + 64 * HH;             // rows 64..79 of 80x64
    ull wA2[8], wB2[8];
#pragma unroll
    for (int p = 0; p < 8; p++) {
        wA2[p] = pk2(w1b[(2 * p) * HH + lane],      w1b[(2 * p + 1) * HH + lane]);
        wB2[p] = pk2(w1b[(2 * p) * HH + lane + 32], w1b[(2 * p + 1) * HH + lane + 32]);
    }
    int nb = blockIdx.x * 8;
    int n = nb + warp;
    int beg = g_off[n], end = g_off[n + 1];
    int bBeg = g_off[nb], bEnd = g_off[nb + 8];
    float accA = 0.f, accB = 0.f;

    for (int cb = bBeg; cb < bEnd; cb += CHK) {
        int cnt = min(CHK, bEnd - cb);
        __syncthreads();
        // cooperative coalesced staging of this chunk's ea + src
        for (int i = tid; i < cnt * 4; i += 256)
            ((float4*)sea)[i] = ((const float4*)g_eaS)[(size_t)cb * 4 + i];
        for (int i = tid; i < cnt; i += 256) ssrc[i] = g_srcS[cb + i];
        __syncthreads();

        int myB = max(beg, cb), myE = min(end, cb + cnt);
        int m = myE - myB;
        if (m > 0) {
            int q0 = myB - cb;
            float ga0, gb0, ga1 = 0.f, gb1 = 0.f, ga2 = 0.f, gb2 = 0.f;
            { int s = ssrc[q0];
              ga0 = g_t1[(size_t)s * HH + lane]; gb0 = g_t1[(size_t)s * HH + lane + 32]; }
            if (m > 1) { int s = ssrc[q0 + 1];
              ga1 = g_t1[(size_t)s * HH + lane]; gb1 = g_t1[(size_t)s * HH + lane + 32]; }
            if (m > 2) { int s = ssrc[q0 + 2];
              ga2 = g_t1[(size_t)s * HH + lane]; gb2 = g_t1[(size_t)s * HH + lane + 32]; }
            for (int q = 0; q < m; q++) {
                float nga = 0.f, ngb = 0.f;
                if (q + 3 < m) {
                    int s = ssrc[q0 + q + 3];
                    nga = g_t1[(size_t)s * HH + lane];
                    ngb = g_t1[(size_t)s * HH + lane + 32];
                }
                const ulonglong2* ep = (const ulonglong2*)(sea + (size_t)(q0 + q) * EAD);
                ull tA = pk2(ga0, 0.f), tB = pk2(gb0, 0.f);
#pragma unroll
                for (int p = 0; p < 4; p++) {
                    ulonglong2 v = ep[p];
                    tA = fma2(v.x, wA2[2 * p], tA);
                    tB = fma2(v.x, wB2[2 * p], tB);
                    tA = fma2(v.y, wA2[2 * p + 1], tA);
                    tB = fma2(v.y, wB2[2 * p + 1], tB);
                }
                float a0, a1, b0, b1;
                upk2(tA, a0, a1); upk2(tB, b0, b1);
                accA += fmaxf(a0 + a1, 0.f);
                accB += fmaxf(b0 + b1, 0.f);
                ga0 = ga1; gb0 = gb1; ga1 = ga2; gb1 = gb2; ga2 = nga; gb2 = ngb;
            }
        }
    }
    g_agg[(size_t)n * HH + lane] = accA;
    g_agg[(size_t)n * HH + lane + 32] = accB;
}

// ---------------- fused node update (packed) ----------------
__global__ __launch_bounds__(256) void kNode(int xSel, const float* __restrict__ xExt,
                                             int xOutSel,
                                             const float* __restrict__ W2,
                                             const float* __restrict__ b2,
                                             const float* __restrict__ V1,
                                             const float* __restrict__ c1,
                                             const float* __restrict__ V2,
                                             const float* __restrict__ c2,
                                             const float* __restrict__ W1n,
                                             const float* __restrict__ b1n,
                                             const float* __restrict__ epsPtr,
                                             const void* __restrict__ batch, int layer) {
    __shared__ __align__(16) ull sA[16][64];
    __shared__ __align__(16) ull sB[16][64];
    int tid = threadIdx.x;
    int c = tid & 63, rs = tid >> 6;
    int base = blockIdx.x * 32;
    const float* X = pickIn(xSel, xExt);
    float* Xo = pickOut(xOutSel);

    float* sAf = (float*)sA;
    for (int idx = tid; idx < 2048; idx += 256) {
        int r = idx >> 6, cc = idx & 63;
        int gr = base + r;
        sAf[((r >> 1) * 64 + cc) * 2 + (r & 1)] = (gr < NN) ? g_agg[(size_t)gr * HH + cc] : 0.f;
    }
    __syncthreads();

    float w[64];
    ull acc[4];

    // ---- stage 1: u = agg@W2 + (1+eps)*x + cnt*b2 ----
#pragma unroll
    for (int k = 0; k < 64; k++) w[k] = W2[k * HH + c];
    gemmP(sA, w, rs, acc);
    {
        float bv = b2[c];
        float ope = 1.f + epsPtr[0];
#pragma unroll
        for (int i = 0; i < 4; i++) {
            int rp = rs + 4 * i;
            int r0 = base + 2 * rp, r1 = r0 + 1;
            float a0, a1; upk2(acc[i], a0, a1);
            float x0 = (r0 < NN) ? X[(size_t)r0 * HH + c] : 0.f;
            float x1 = (r1 < NN) ? X[(size_t)r1 * HH + c] : 0.f;
            float n0 = (r0 < NN) ? (float)g_cnt[r0] : 0.f;
            float n1 = (r1 < NN) ? (float)g_cnt[r1] : 0.f;
            a0 += ope * x0 + n0 * bv;
            a1 += ope * x1 + n1 * bv;
            sB[rp][c] = pk2(a0, a1);
        }
    }
    __syncthreads();

    // ---- stage 2: h = relu(u@V1 + c1) ----
#pragma unroll
    for (int k = 0; k < 64; k++) w[k] = V1[k * HH + c];
    gemmP(sB, w, rs, acc);
    {
        float bv = c1[c];
#pragma unroll
        for (int i = 0; i < 4; i++) {
            float a0, a1; upk2(acc[i], a0, a1);
            sA[rs + 4 * i][c] = pk2(fmaxf(a0 + bv, 0.f), fmaxf(a1 + bv, 0.f));
        }
    }
    __syncthreads();

    // ---- stage 3: xn = h@V2 + c2 ; write x_next + pool atomics ----
#pragma unroll
    for (int k = 0; k < 64; k++) w[k] = V2[k * HH + c];
    gemmP(sA, w, rs, acc);
    {
        float bv = c2[c];
        int f64 = g_flag64;
#pragma unroll
        for (int i = 0; i < 4; i++) {
            int rp = rs + 4 * i;
            int r0 = base + 2 * rp, r1 = r0 + 1;
            float a0, a1; upk2(acc[i], a0, a1);
            float v0 = a0 + bv, v1 = a1 + bv;
            sB[rp][c] = pk2(v0, v1);
            if (r0 < NN) {
                Xo[(size_t)r0 * HH + c] = v0;
                int g = f64 ? (int)((const long long*)batch)[r0] : ((const int*)batch)[r0];
                atomicAdd(&g_pool[(size_t)g * FD + layer * HH + c], v0);
            }
            if (r1 < NN) {
                Xo[(size_t)r1 * HH + c] = v1;
                int g = f64 ? (int)((const long long*)batch)[r1] : ((const int*)batch)[r1];
                atomicAdd(&g_pool[(size_t)g * FD + layer * HH + c], v1);
            }
        }
    }

    // ---- stage 4: t1_next = xn@W1a_next + b1_next ----
    if (W1n) {
        __syncthreads();
#pragma unroll
        for (int k = 0; k < 64; k++) w[k] = W1n[k * HH + c];
        gemmP(sB, w, rs, acc);
        float bv = b1n[c];
#pragma unroll
        for (int i = 0; i < 4; i++) {
            int r0 = base + 2 * (rs + 4 * i), r1 = r0 + 1;
            float a0, a1; upk2(acc[i], a0, a1);
            if (r0 < NN) g_t1[(size_t)r0 * HH + c] = a0 + bv;
            if (r1 < NN) g_t1[(size_t)r1 * HH + c] = a1 + bv;
        }
    }
}

// ---------------- final MLP ----------------
__global__ __launch_bounds__(320) void kFinal(const float* __restrict__ fw1,
                                              const float* __restrict__ fb1,
                                              const float* __restrict__ fw2,
                                              const float* __restrict__ fb2,
                                              float* __restrict__ out) {
    __shared__ float fsh[8][FD];
    __shared__ float hsh[8][FD];
    int tid = threadIdx.x;
    int gbase = blockIdx.x * 8;
    for (int i = tid; i < 8 * FD; i += 320) {
        int gg = i / FD, k = i % FD;
        fsh[gg][k] = g_pool[(size_t)(gbase + gg) * FD + k];
    }
    __syncthreads();
    float acc[8] = {0, 0, 0, 0, 0, 0, 0, 0};
    for (int k = 0; k < FD; k++) {
        float w = fw1[(size_t)k * FD + tid];
#pragma unroll
        for (int gg = 0; gg < 8; gg++) acc[gg] = fmaf(fsh[gg][k], w, acc[gg]);
    }
    float b = fb1[tid];
#pragma unroll
    for (int gg = 0; gg < 8; gg++) hsh[gg][tid] = fmaxf(acc[gg] + b, 0.f);
    __syncthreads();
    int warp = tid >> 5, lane = tid & 31;
    if (warp < 8) {
        float s = 0.f;
        for (int k = lane; k < FD; k += 32) s += hsh[warp][k] * fw2[k];
#pragma unroll
        for (int o = 16; o; o >>= 1) s += __shfl_down_sync(0xffffffffu, s, o);
        if (lane == 0) out[gbase + warp] = s + fb2[0];
    }
}

// ---------------- launch ----------------
extern "C" void kernel_launch(void* const* d_in, const int* in_sizes, int n_in,
                              void* d_out, int out_size) {
    const float* x    = (const float*)d_in[0];
    const void*  ei   = d_in[1];
    const float* ea   = (const float*)d_in[2];
    const void*  bat  = d_in[3];
    const float* n2w1 = (const float*)d_in[4];
    const float* n2b1 = (const float*)d_in[5];
    const float* n2w2 = (const float*)d_in[6];
    const float* n2b2 = (const float*)d_in[7];
    const float* n1w1 = (const float*)d_in[8];
    const float* n1b1 = (const float*)d_in[9];
    const float* n1w2 = (const float*)d_in[10];
    const float* n1b2 = (const float*)d_in[11];
    const float* fw1  = (const float*)d_in[12];
    const float* fb1  = (const float*)d_in[13];
    const float* fw2  = (const float*)d_in[14];
    const float* fb2  = (const float*)d_in[15];
    const float* eps  = (const float*)d_in[16];

    kDetect<<<1, 1>>>(ei);
    kZero<<<(GG * FD + 255) / 256, 256>>>();
    kCount<<<EE / 256, 256>>>(ei);
    // launch #4 = kT1 (scan-independent) so ncu captures the packed GEMM core
    kT1<<<(NN + 31) / 32, 256>>>(x, n2w1, n2b1);
    kScanA<<<NBLK, 1024>>>();
    kScanB<<<1, 32>>>();
    kScanC<<<NBLK, 1024>>>();
    kScatter<<<EE / 256, 256>>>(ei, ea);

    int xSel = 4;
    const float* xPtr = x;
    for (int l = 0; l < LLAY; l++) {
        const float* W2 = n2w2 + (size_t)l * HH * HH;
        const float* b2 = n2b2 + (size_t)l * HH;
        const float* V1 = n1w1 + (size_t)l * HH * HH;
        const float* c1 = n1b1 + (size_t)l * HH;
        const float* V2 = n1w2 + (size_t)l * HH * HH;
        const float* c2 = n1b2 + (size_t)l * HH;
        const float* W1n = (l + 1 < LLAY) ? n2w1 + (size_t)(l + 1) * IN2 * HH : nullptr;
        const float* b1n = (l + 1 < LLAY) ? n2b1 + (size_t)(l + 1) * HH : nullptr;
        int xNextSel = (l & 1) ? 3 : 2;

        kAgg<<<NN / 8, 256>>>(n2w1 + (size_t)l * IN2 * HH);
        kNode<<<(NN + 31) / 32, 256>>>(xSel, xPtr, xNextSel, W2, b2, V1, c1, V2, c2,
                                       W1n, b1n, eps, bat, l);

        xSel = xNextSel;
        xPtr = nullptr;
    }

    kFinal<<<GG / 8, 320>>>(fw1, fb1, fw2, fb2, (float*)d_out);
}